// round 1
// baseline (speedup 1.0000x reference)
#include <cuda_runtime.h>
#include <math.h>

#define HH 512
#define WW 512
#define PLANE (512*512)
#define SHAPE_OFF (1*PLANE)
#define SIZE_OFF  (1025*PLANE)
#define HEAT_OFF  (1027*PLANE)
#define NPTS 10
#define MM 128

// packed argmax state: hi32 = orderable float key, lo32 = ~flat_index
__device__ unsigned long long g_argmax[NPTS];

__device__ __forceinline__ unsigned int fkey(float v) {
    unsigned int b = __float_as_uint(v);
    return (b & 0x80000000u) ? ~b : (b | 0x80000000u);
}

__global__ void init_kernel() {
    if (threadIdx.x < NPTS) g_argmax[threadIdx.x] = 0ULL;
}

// 64 blocks per heatmap, 256 threads, float4 loads (16 elements/thread)
__global__ void argmax_kernel(const float* __restrict__ feat) {
    int hm    = blockIdx.x >> 6;
    int chunk = blockIdx.x & 63;
    const float* heat = feat + HEAT_OFF + (size_t)hm * PLANE;
    int base = chunk * 4096;

    unsigned long long best = 0ULL;
#pragma unroll
    for (int j = 0; j < 4; j++) {
        int e = base + ((j * 256 + threadIdx.x) << 2);
        float4 v = *reinterpret_cast<const float4*>(heat + e);
        float vals[4] = {v.x, v.y, v.z, v.w};
#pragma unroll
        for (int m = 0; m < 4; m++) {
            unsigned long long p =
                ((unsigned long long)fkey(vals[m]) << 32) |
                (unsigned int)(~(unsigned int)(e + m));
            best = (p > best) ? p : best;
        }
    }

    __shared__ unsigned long long s[256];
    s[threadIdx.x] = best;
    __syncthreads();
#pragma unroll
    for (int stride = 128; stride > 0; stride >>= 1) {
        if (threadIdx.x < stride) {
            unsigned long long o = s[threadIdx.x + stride];
            if (o > s[threadIdx.x]) s[threadIdx.x] = o;
        }
        __syncthreads();
    }
    if (threadIdx.x == 0) atomicMax(&g_argmax[hm], s[0]);
}

// grid (NPTS, 8): each block computes 16 output rows of one point. 256 threads.
__global__ void compute_kernel(const float* __restrict__ feat,
                               float* __restrict__ out) {
    __shared__ float s_vec[1024];       // 32x32 shape vector
    __shared__ float s_rows[16 * 32];   // y-interpolated rows for this slice

    int pt = blockIdx.x;
    int r0 = blockIdx.y * 16;

    unsigned long long packed = g_argmax[pt];
    int idx = (int)(~(unsigned int)(packed & 0xFFFFFFFFu));
    int py = idx >> 9;      // idx / 512
    int px = idx & 511;     // idx % 512

    float hv = fabsf(feat[SIZE_OFF + py * WW + px]);
    float wv = fabsf(feat[SIZE_OFF + PLANE + py * WW + px]);
    int h = min(max((int)hv, 1), MM);
    int w = min(max((int)wv, 1), MM);
    float hf = (float)h, wf = (float)w;

    // gather 1024 scattered channel values (stride 1MB) into shared
    for (int c = threadIdx.x; c < 1024; c += blockDim.x)
        s_vec[c] = feat[SHAPE_OFF + (size_t)c * PLANE + py * WW + px];
    __syncthreads();

    // y-interp for our 16 rows
    for (int i = threadIdx.x; i < 16 * 32; i += blockDim.x) {
        int r = r0 + (i >> 5);
        int x = i & 31;
        float sy = ((float)r + 0.5f) * 32.0f / hf - 0.5f;
        sy = fminf(fmaxf(sy, 0.0f), 31.0f);
        int y0 = (int)floorf(sy);
        int y1 = min(y0 + 1, 31);
        float wy = sy - (float)y0;
        s_rows[i] = s_vec[y0 * 32 + x] * (1.0f - wy) + s_vec[y1 * 32 + x] * wy;
    }
    __syncthreads();

    const float* sal = feat;  // channel 0
    float* o = out + (size_t)pt * (MM * MM) + (size_t)r0 * MM;
    int h2 = h >> 1, w2 = w >> 1;

    for (int i = threadIdx.x; i < 16 * MM; i += blockDim.x) {
        int rl = i >> 7;        // local row 0..15
        int c  = i & 127;
        int r  = r0 + rl;
        float sx = ((float)c + 0.5f) * 32.0f / wf - 0.5f;
        sx = fminf(fmaxf(sx, 0.0f), 31.0f);
        int x0 = (int)floorf(sx);
        int x1 = min(x0 + 1, 31);
        float wx = sx - (float)x0;
        float v = s_rows[rl * 32 + x0] * (1.0f - wx) +
                  s_rows[rl * 32 + x1] * wx;
        float lv = 1.0f / (1.0f + __expf(-v));
        int gr = py - h2 + r;
        int gc = px - w2 + c;
        bool valid = (r < h) && (c < w) &&
                     (gr >= 0) && (gr < HH) && (gc >= 0) && (gc < WW);
        float s = valid ? sal[gr * WW + gc] : 0.0f;
        o[i] = valid ? lv * s : 0.0f;
    }
}

extern "C" void kernel_launch(void* const* d_in, const int* in_sizes, int n_in,
                              void* d_out, int out_size) {
    const float* feat = (const float*)d_in[0];
    float* out = (float*)d_out;

    init_kernel<<<1, 32>>>();
    argmax_kernel<<<NPTS * 64, 256>>>(feat);
    dim3 g(NPTS, 8);
    compute_kernel<<<g, 256>>>(feat, out);
}